// round 13
// baseline (speedup 1.0000x reference)
#include <cuda_runtime.h>
#include <cuda_fp16.h>
#include <math.h>
#include <stdint.h>

#define Bn 512
#define Tn 256
#define Cn 192
#define Hn 64

// Scratch (device globals = sanctioned alloc-free mechanism). Packed half2 words.
__device__ unsigned g_q[(size_t)Bn * Tn * 32];   // [b*t][32w] = [t][64h] half, pre-scaled
__device__ unsigned g_k[(size_t)Bn * Tn * 32];   // [b][t][64h] half
__device__ unsigned g_vT[(size_t)Bn * 64 * 128]; // [b][64h][256t] half
__device__ float g_pos[Tn * 128];                // [t][ pos_k | pos_q ]  fp32
__device__ float g_bias[Tn * Tn];                // fp32 exact

// ---------------------------------------------------------------------------
// fp16 m16n8k16: A = 4 packed-half2 regs, B = 2, C/D fp32 x4
__device__ __forceinline__ void mma_f16(float c[4], const unsigned a[4],
                                        unsigned b0, unsigned b1) {
    asm volatile(
        "mma.sync.aligned.m16n8k16.row.col.f32.f16.f16.f32 "
        "{%0,%1,%2,%3}, {%4,%5,%6,%7}, {%8,%9}, {%0,%1,%2,%3};"
        : "+f"(c[0]), "+f"(c[1]), "+f"(c[2]), "+f"(c[3])
        : "r"(a[0]), "r"(a[1]), "r"(a[2]), "r"(a[3]), "r"(b0), "r"(b1));
}

// pack two fp32 -> half2 word, lo half = first arg
__device__ __forceinline__ unsigned packh2(float lo, float hi) {
    unsigned p;
    asm("cvt.rn.f16x2.f32 %0, %1, %2;" : "=r"(p) : "f"(hi), "f"(lo));
    return p;
}

__device__ __forceinline__ unsigned smaddr(const void* p) {
    return (unsigned)__cvta_generic_to_shared(p);
}
#define CP_ASYNC16(dst, src) \
    asm volatile("cp.async.ca.shared.global [%0], [%1], 16;" :: "r"(dst), "l"(src))
#define CP_COMMIT() asm volatile("cp.async.commit_group;")

// ---------------------------------------------------------------------------
// Kernel 1: FUSED QKV projection — x read ONCE. grid 1024 (128-row tiles),
// 256 thr, 2 CTAs/SM. Warp = 16 rows x 64 cols x 3 sels (A-frags shared
// across sels). W (all 3) fragment-native uint2 (one conflict-free LDS.64
// per mma), 73.7KB. x in 16-k chunks, stride 24 (banks 24gq+2tg distinct),
// TRIPLE-buffered cp.async, one __syncthreads per chunk. 108KB smem.
// ---------------------------------------------------------------------------
#define XKS 24
__global__ __launch_bounds__(256, 2) void qkv_fused_kernel(const float* __restrict__ x,
                                                           const float* __restrict__ Wq,
                                                           const float* __restrict__ Wk,
                                                           const float* __restrict__ Wv) {
    extern __shared__ float sm[];
    uint2* Wf = (uint2*)sm;                 // 9216 uint2 = 73728 B
    float* xb = sm + 18432;                 // 3 bufs x 3072 floats

    const int by = blockIdx.x;
    const int tid = threadIdx.x;
    const float* __restrict__ xc = x + (size_t)by * 128 * 192;

    // prologue: stage x chunks 0,1 (each: 128 rows x 4 x 16B)
#pragma unroll
    for (int cc = 0; cc < 2; cc++) {
        float* dst = xb + cc * 3072;
        const float* src = xc + cc * 16;
        for (int f = tid; f < 512; f += 256) {
            int r = f >> 2, c4 = f & 3;
            CP_ASYNC16(smaddr(dst + r * XKS + c4 * 4), src + r * 192 + c4 * 4);
        }
        CP_COMMIT();
    }

    // stage all 3 Ws fragment-native: Wf[((s*12+kk)*8+nt)*32 + 8*tg2+gq2]
    for (int idx = tid; idx < 9216; idx += 256) {
        int s = idx / 3072;
        int r = idx - s * 3072;
        int kk = r >> 8;
        int r2 = r & 255;
        int nt = r2 >> 5;
        int lane2 = r2 & 31;
        int tg2 = lane2 >> 3, gq2 = lane2 & 7;
        const float* __restrict__ W = (s == 0) ? Wq : ((s == 1) ? Wk : Wv);
        int n = nt * 8 + gq2;
        int k0 = kk * 16 + 2 * tg2;
        unsigned b0 = packh2(W[k0 * 64 + n], W[(k0 + 1) * 64 + n]);
        unsigned b1 = packh2(W[(k0 + 8) * 64 + n], W[(k0 + 9) * 64 + n]);
        Wf[idx] = make_uint2(b0, b1);
    }

    const int w = tid >> 5, lane = tid & 31;
    const int gq = lane >> 2, tg = lane & 3;

    float acc[3][8][4];
#pragma unroll
    for (int s = 0; s < 3; s++)
#pragma unroll
        for (int n = 0; n < 8; n++)
#pragma unroll
            for (int i = 0; i < 4; i++) acc[s][n][i] = 0.0f;

    for (int c = 0; c < 12; c++) {
        if (c < 11) { asm volatile("cp.async.wait_group 1;"); }
        else        { asm volatile("cp.async.wait_group 0;"); }
        __syncthreads();   // publishes chunk c; also fences reads of buf[(c+2)%3] from iter c-1

        if (c + 2 < 12) {
            float* dst = xb + ((c + 2) % 3) * 3072;
            const float* src = xc + (c + 2) * 16;
            for (int f = tid; f < 512; f += 256) {
                int r = f >> 2, c4 = f & 3;
                CP_ASYNC16(smaddr(dst + r * XKS + c4 * 4), src + r * 192 + c4 * 4);
            }
            CP_COMMIT();
        }

        const float* xs = xb + (c % 3) * 3072 + (w * 16) * XKS;
        unsigned a0[4];
        {
            float2 v;
            v = *(const float2*)(xs + gq * XKS + 2 * tg);           a0[0] = packh2(v.x, v.y);
            v = *(const float2*)(xs + (gq + 8) * XKS + 2 * tg);     a0[1] = packh2(v.x, v.y);
            v = *(const float2*)(xs + gq * XKS + 8 + 2 * tg);       a0[2] = packh2(v.x, v.y);
            v = *(const float2*)(xs + (gq + 8) * XKS + 8 + 2 * tg); a0[3] = packh2(v.x, v.y);
        }
#pragma unroll
        for (int s = 0; s < 3; s++) {
            const uint2* wp = Wf + s * 3072 + c * 256 + 8 * tg + gq;
#pragma unroll
            for (int nt = 0; nt < 8; nt++) {
                uint2 wv = wp[nt * 32];
                mma_f16(acc[s][nt], a0, wv.x, wv.y);
            }
        }
    }

    // Epilogues (16-row tiles; round-11-verified index math)
    const int b = by >> 1;
    const int tt = (by & 1) * 128 + w * 16 + gq;     // global t within batch
    {
        const float qs = rsqrtf(192.0f);
        unsigned* qo = g_q + (size_t)b * 256 * 32;
#pragma unroll
        for (int nt = 0; nt < 8; nt++) {
            int wi = nt * 4 + tg;
            qo[tt * 32 + wi]       = packh2(acc[0][nt][0] * qs, acc[0][nt][1] * qs);
            qo[(tt + 8) * 32 + wi] = packh2(acc[0][nt][2] * qs, acc[0][nt][3] * qs);
        }
    }
    {
        unsigned* ko = g_k + (size_t)b * 256 * 32;
#pragma unroll
        for (int nt = 0; nt < 8; nt++) {
            int wi = nt * 4 + tg;
            ko[tt * 32 + wi]       = packh2(acc[1][nt][0], acc[1][nt][1]);
            ko[(tt + 8) * 32 + wi] = packh2(acc[1][nt][2], acc[1][nt][3]);
        }
    }
    {
        // v -> [h][t] half: adjacent t in lanes gq, gq^1 (lane^4); even-gq packs.
        unsigned* vo = g_vT + (size_t)b * 8192;
        const bool even = ((gq & 1) == 0);
#pragma unroll
        for (int nt = 0; nt < 8; nt++) {
            int cc = nt * 8 + 2 * tg;
            float a0v = acc[2][nt][0], a1v = acc[2][nt][1];
            float a2v = acc[2][nt][2], a3v = acc[2][nt][3];
            float p0 = __shfl_xor_sync(0xffffffffu, a0v, 4);
            float p1 = __shfl_xor_sync(0xffffffffu, a1v, 4);
            float p2 = __shfl_xor_sync(0xffffffffu, a2v, 4);
            float p3 = __shfl_xor_sync(0xffffffffu, a3v, 4);
            if (even) {
                vo[cc * 128 + (tt >> 1)]             = packh2(a0v, p0);
                vo[(cc + 1) * 128 + (tt >> 1)]       = packh2(a1v, p1);
                vo[cc * 128 + ((tt + 8) >> 1)]       = packh2(a2v, p2);
                vo[(cc + 1) * 128 + ((tt + 8) >> 1)] = packh2(a3v, p3);
            }
        }
    }
}

// ---------------------------------------------------------------------------
// Kernel 2 + 3: positional projections and bias (tiny, fp32 exact)
// ---------------------------------------------------------------------------
__global__ __launch_bounds__(256) void pos_kernel(const float* __restrict__ pe,
                                                  const float* __restrict__ Wk,
                                                  const float* __restrict__ Wq) {
    int idx = blockIdx.x * 256 + threadIdx.x;
    int t = idx >> 7;
    int j = idx & 127;
    const float* __restrict__ W = (j < 64) ? Wk : Wq;
    int col = j & 63;
    float s = 0.0f;
#pragma unroll 4
    for (int c = 0; c < 192; c++) s = fmaf(pe[t * 192 + c], W[c * 64 + col], s);
    g_pos[idx] = s;
}

__global__ __launch_bounds__(256) void bias_kernel() {
    int i = blockIdx.x;
    int j = threadIdx.x;
    float s = 0.0f;
#pragma unroll 4
    for (int h = 0; h < 64; h++)
        s = fmaf(g_pos[i * 128 + h], g_pos[j * 128 + 64 + h], s);
    g_bias[i * 256 + j] = s;
}

// ---------------------------------------------------------------------------
// Kernel 4: flash-block attention (round-12 version, 65.0us measured).
// ---------------------------------------------------------------------------
#define KSW 36
#define VSW 20
#define PSW 20
__global__ __launch_bounds__(256, 2) void attn_f16_kernel(float* __restrict__ out) {
    extern __shared__ unsigned smw[];
    unsigned* kbuf[2] = { smw, smw + 1152 };          // 32*36 words each
    unsigned* vbuf[2] = { smw + 2304, smw + 3584 };   // 64*20 words each
    unsigned* p_s = smw + 4864;                       // 8 * 16*20 words

    const int qb = blockIdx.x;
    const int b  = blockIdx.y;
    const int tid = threadIdx.x, w = tid >> 5, lane = tid & 31;
    const int gq = lane >> 2, tg = lane & 3;
    const int nj = (qb + 1) * 4;

    const unsigned* __restrict__ kg = g_k + (size_t)b * 8192;    // [t][32w]
    const unsigned* __restrict__ vg = g_vT + (size_t)b * 8192;   // [h][128w]

    const int rowg = qb * 128 + gq * 8 + w;
    const int row2 = rowg + 64;

    // Q fragments (packed half2): 16 x 32-bit loads
    unsigned qa[4][4];
    {
        const unsigned* __restrict__ qh = g_q + ((size_t)b * 256 + qb * 128) * 32;
        const int r0 = gq * 8 + w, r1 = r0 + 64;
#pragma unroll
        for (int kk = 0; kk < 4; kk++) {
            qa[kk][0] = qh[r0 * 32 + kk * 8 + tg];
            qa[kk][1] = qh[r1 * 32 + kk * 8 + tg];
            qa[kk][2] = qh[r0 * 32 + kk * 8 + tg + 4];
            qa[kk][3] = qh[r1 * 32 + kk * 8 + tg + 4];
        }
    }

    float o[8][4];
#pragma unroll
    for (int n = 0; n < 8; n++)
#pragma unroll
        for (int i = 0; i < 4; i++) o[n][i] = 0.0f;
    float m0 = -1e30f, m1 = -1e30f, l0 = 0.0f, l1 = 0.0f;

    unsigned* pw = p_s + w * 320;

    // Prologue: stage tile 0. K: 32 rows x 8 chunks; V: 64 rows x 4 chunks.
    for (int f = tid; f < 512; f += 256) {
        if (f < 256) {
            int r = f >> 3, c8 = f & 7;
            CP_ASYNC16(smaddr(kbuf[0] + r * KSW + c8 * 4), kg + r * 32 + c8 * 4);
        } else {
            int g = f - 256;
            int h = g >> 2, c4 = g & 3;
            CP_ASYNC16(smaddr(vbuf[0] + h * VSW + c4 * 4), vg + h * 128 + c4 * 4);
        }
    }
    CP_COMMIT();

    int buf = 0;
    for (int jt = 0; jt < nj; jt++) {
        const int j0 = jt * 32;
        asm volatile("cp.async.wait_group 0;");
        __syncthreads();

        if (jt + 1 < nj) {
            const int jn = j0 + 32;
            unsigned* kn = kbuf[buf ^ 1];
            unsigned* vn = vbuf[buf ^ 1];
            for (int f = tid; f < 512; f += 256) {
                if (f < 256) {
                    int r = f >> 3, c8 = f & 7;
                    CP_ASYNC16(smaddr(kn + r * KSW + c8 * 4),
                               kg + (jn + r) * 32 + c8 * 4);
                } else {
                    int g = f - 256;
                    int h = g >> 2, c4 = g & 3;
                    CP_ASYNC16(smaddr(vn + h * VSW + c4 * 4),
                               vg + h * 128 + (jn >> 1) + c4 * 4);
                }
            }
            CP_COMMIT();
        }

        const unsigned* kb = kbuf[buf];
        const unsigned* vb = vbuf[buf];

        // Hoisted bias loads (independent of the mma chain below)
        float2 bv0[4], bv1[4];
        {
            const float* __restrict__ br0 = g_bias + (size_t)rowg * 256 + j0;
            const float* __restrict__ br1 = g_bias + (size_t)row2 * 256 + j0;
#pragma unroll
            for (int nt = 0; nt < 4; nt++) {
                int c = nt * 8 + 2 * tg;
                bv0[nt] = *(const float2*)(br0 + c);
                bv1[nt] = *(const float2*)(br1 + c);
            }
        }

        // S = Q K^T  (q pre-scaled): 16 mmas
        float s[4][4];
#pragma unroll
        for (int n = 0; n < 4; n++)
#pragma unroll
            for (int i = 0; i < 4; i++) s[n][i] = 0.0f;
#pragma unroll
        for (int kk = 0; kk < 4; kk++) {
#pragma unroll
            for (int nt = 0; nt < 4; nt++) {
                const unsigned* kb2 = kb + (nt * 8 + gq) * KSW + kk * 8 + tg;
                mma_f16(s[nt], qa[kk], kb2[0], kb2[4]);
            }
        }

        // + bias, causal mask
#pragma unroll
        for (int nt = 0; nt < 4; nt++) {
            int c = nt * 8 + 2 * tg;
            int col = j0 + c;
            s[nt][0] = (col     <= rowg) ? (s[nt][0] + bv0[nt].x) : -1e30f;
            s[nt][1] = (col + 1 <= rowg) ? (s[nt][1] + bv0[nt].y) : -1e30f;
            s[nt][2] = (col     <= row2) ? (s[nt][2] + bv1[nt].x) : -1e30f;
            s[nt][3] = (col + 1 <= row2) ? (s[nt][3] + bv1[nt].y) : -1e30f;
        }

        // online softmax
        float mx0 = -1e30f, mx1 = -1e30f;
#pragma unroll
        for (int nt = 0; nt < 4; nt++) {
            mx0 = fmaxf(mx0, fmaxf(s[nt][0], s[nt][1]));
            mx1 = fmaxf(mx1, fmaxf(s[nt][2], s[nt][3]));
        }
        mx0 = fmaxf(mx0, __shfl_xor_sync(0xffffffffu, mx0, 1));
        mx0 = fmaxf(mx0, __shfl_xor_sync(0xffffffffu, mx0, 2));
        mx1 = fmaxf(mx1, __shfl_xor_sync(0xffffffffu, mx1, 1));
        mx1 = fmaxf(mx1, __shfl_xor_sync(0xffffffffu, mx1, 2));
        float mn0 = fmaxf(m0, mx0), mn1 = fmaxf(m1, mx1);
        float al0 = __expf(m0 - mn0), al1 = __expf(m1 - mn1);
        m0 = mn0; m1 = mn1;

        float sum0 = 0.0f, sum1 = 0.0f;
        float e[4][4];
#pragma unroll
        for (int nt = 0; nt < 4; nt++) {
            e[nt][0] = __expf(s[nt][0] - mn0);
            e[nt][1] = __expf(s[nt][1] - mn0);
            e[nt][2] = __expf(s[nt][2] - mn1);
            e[nt][3] = __expf(s[nt][3] - mn1);
            sum0 += e[nt][0] + e[nt][1];
            sum1 += e[nt][2] + e[nt][3];
        }
        sum0 += __shfl_xor_sync(0xffffffffu, sum0, 1);
        sum0 += __shfl_xor_sync(0xffffffffu, sum0, 2);
        sum1 += __shfl_xor_sync(0xffffffffu, sum1, 1);
        sum1 += __shfl_xor_sync(0xffffffffu, sum1, 2);
        l0 = l0 * al0 + sum0;
        l1 = l1 * al1 + sum1;

#pragma unroll
        for (int nt = 0; nt < 8; nt++) {
            o[nt][0] *= al0; o[nt][1] *= al0;
            o[nt][2] *= al1; o[nt][3] *= al1;
        }

        // stage P (packed half2) per-warp, stride 20 words
#pragma unroll
        for (int nt = 0; nt < 4; nt++) {
            pw[gq * PSW + nt * 4 + tg]       = packh2(e[nt][0], e[nt][1]);
            pw[(gq + 8) * PSW + nt * 4 + tg] = packh2(e[nt][2], e[nt][3]);
        }
        __syncwarp();

        // O += P V : 16 mmas
#pragma unroll
        for (int ks = 0; ks < 2; ks++) {
            unsigned pa[4];
            pa[0] = pw[gq * PSW + ks * 8 + tg];
            pa[1] = pw[(gq + 8) * PSW + ks * 8 + tg];
            pa[2] = pw[gq * PSW + ks * 8 + tg + 4];
            pa[3] = pw[(gq + 8) * PSW + ks * 8 + tg + 4];
#pragma unroll
            for (int nt = 0; nt < 8; nt++) {
                const unsigned* vb2 = vb + (nt * 8 + gq) * VSW + ks * 8 + tg;
                mma_f16(o[nt], pa, vb2[0], vb2[4]);
            }
        }
        __syncwarp();
        // no bottom __syncthreads — next iteration's top barrier orders restaging
        buf ^= 1;
    }

    float inv0 = 1.0f / l0, inv1 = 1.0f / l1;
    float* ob = out + ((size_t)b * 256) * 64;
#pragma unroll
    for (int nt = 0; nt < 8; nt++) {
        int c = nt * 8 + 2 * tg;
        *(float2*)(ob + (size_t)rowg * 64 + c) =
            make_float2(o[nt][0] * inv0, o[nt][1] * inv0);
        *(float2*)(ob + (size_t)row2 * 64 + c) =
            make_float2(o[nt][2] * inv1, o[nt][3] * inv1);
    }
}

// ---------------------------------------------------------------------------
extern "C" void kernel_launch(void* const* d_in, const int* in_sizes, int n_in,
                              void* d_out, int out_size) {
    const float* x  = (const float*)d_in[0];
    const float* Wk = (const float*)d_in[1];
    const float* Wq = (const float*)d_in[2];
    const float* Wv = (const float*)d_in[3];
    const float* pe = (const float*)d_in[4];
    float* out = (float*)d_out;
    (void)in_sizes; (void)n_in; (void)out_size;

    static bool attr_set = false;
    if (!attr_set) {
        cudaFuncSetAttribute(qkv_fused_kernel,
                             cudaFuncAttributeMaxDynamicSharedMemorySize, 110592);
        cudaFuncSetAttribute(attn_f16_kernel,
                             cudaFuncAttributeMaxDynamicSharedMemorySize, 29696);
        attr_set = true;
    }

    qkv_fused_kernel<<<1024, 256, 110592>>>(x, Wq, Wk, Wv);
    pos_kernel<<<128, 256>>>(pe, Wk, Wq);
    bias_kernel<<<256, 256>>>();
    attn_f16_kernel<<<dim3(2, 512), 256, 29696>>>(out);
}

// round 14
// speedup vs baseline: 1.1391x; 1.1391x over previous
#include <cuda_runtime.h>
#include <cuda_fp16.h>
#include <math.h>
#include <stdint.h>

#define Bn 512
#define Tn 256
#define Cn 192
#define Hn 64

// Scratch (device globals = sanctioned alloc-free mechanism). Packed half2 words.
__device__ unsigned g_q[(size_t)Bn * Tn * 32];   // [b*t][32w] = [t][64h] half, pre-scaled
__device__ unsigned g_k[(size_t)Bn * Tn * 32];   // [b][t][64h] half
__device__ unsigned g_vT[(size_t)Bn * 64 * 128]; // [b][64h][256t] half
__device__ float g_pos[Tn * 128];                // [t][ pos_k | pos_q ]  fp32
__device__ float g_bias[Tn * Tn];                // fp32 exact

// ---------------------------------------------------------------------------
// fp16 m16n8k16: A = 4 packed-half2 regs, B = 2, C/D fp32 x4
__device__ __forceinline__ void mma_f16(float c[4], const unsigned a[4],
                                        unsigned b0, unsigned b1) {
    asm volatile(
        "mma.sync.aligned.m16n8k16.row.col.f32.f16.f16.f32 "
        "{%0,%1,%2,%3}, {%4,%5,%6,%7}, {%8,%9}, {%0,%1,%2,%3};"
        : "+f"(c[0]), "+f"(c[1]), "+f"(c[2]), "+f"(c[3])
        : "r"(a[0]), "r"(a[1]), "r"(a[2]), "r"(a[3]), "r"(b0), "r"(b1));
}

// pack two fp32 -> half2 word, lo half = first arg
__device__ __forceinline__ unsigned packh2(float lo, float hi) {
    unsigned p;
    asm("cvt.rn.f16x2.f32 %0, %1, %2;" : "=r"(p) : "f"(hi), "f"(lo));
    return p;
}

__device__ __forceinline__ unsigned smaddr(const void* p) {
    return (unsigned)__cvta_generic_to_shared(p);
}
#define CP_ASYNC16(dst, src) \
    asm volatile("cp.async.ca.shared.global [%0], [%1], 16;" :: "r"(dst), "l"(src))
#define CP_COMMIT() asm volatile("cp.async.commit_group;")

// ---------------------------------------------------------------------------
// Kernel 1: QKV projection, fp16 m16n8k16 (round-12 version, proven).
// grid (3, 512): x = sel, y = b. 8 warps x (32 rows x 64 cols), k=192 in 6
// chunks of 32. W packed half2 [96 k2][72w]; x cp.async fp32 [256][40]
// double-buffered. 109.6KB smem -> 2 CTAs/SM, natural register allocation.
// ---------------------------------------------------------------------------
#define WST 72
#define XST 40
__global__ __launch_bounds__(256, 2) void qkv_f16_kernel(const float* __restrict__ x,
                                                         const float* __restrict__ Wq,
                                                         const float* __restrict__ Wk,
                                                         const float* __restrict__ Wv) {
    extern __shared__ float sm[];
    unsigned* W_sh = (unsigned*)sm;                        // 96*72 words
    float* bufs[2] = { sm + 6912, sm + 6912 + 10240 };     // 256*40 each

    const int sel = blockIdx.x;
    const int b = blockIdx.y;
    const int tid = threadIdx.x;
    const float* __restrict__ W = (sel == 0) ? Wq : ((sel == 1) ? Wk : Wv);
    const float* __restrict__ xc = x + (size_t)b * 256 * 192;

    // prologue: chunk 0 (k 0..31)
    for (int f = tid; f < 2048; f += 256) {
        int r = f >> 3, c4 = f & 7;
        CP_ASYNC16(smaddr(bufs[0] + r * XST + c4 * 4), xc + r * 192 + c4 * 4);
    }
    CP_COMMIT();

    // stage W packed half2: word (k2, n) = (W[2k2][n], W[2k2+1][n])
    for (int idx = tid; idx < 6144; idx += 256) {
        int k2 = idx >> 6, n = idx & 63;
        W_sh[k2 * WST + n] = packh2(W[(2 * k2) * 64 + n], W[(2 * k2 + 1) * 64 + n]);
    }

    const int w = tid >> 5, lane = tid & 31;
    const int gq = lane >> 2, tg = lane & 3;

    float acc[2][8][4];
#pragma unroll
    for (int r = 0; r < 2; r++)
#pragma unroll
        for (int n = 0; n < 8; n++)
#pragma unroll
            for (int i = 0; i < 4; i++) acc[r][n][i] = 0.0f;

    int buf = 0;
    for (int c = 0; c < 6; c++) {
        if (c < 5) {
            const float* src = xc + (c + 1) * 32;
            float* dst = bufs[buf ^ 1];
            for (int f = tid; f < 2048; f += 256) {
                int r = f >> 3, c4 = f & 7;
                CP_ASYNC16(smaddr(dst + r * XST + c4 * 4), src + r * 192 + c4 * 4);
            }
            CP_COMMIT();
            asm volatile("cp.async.wait_group 1;");
        } else {
            asm volatile("cp.async.wait_group 0;");
        }
        __syncthreads();

        const float* xs = bufs[buf] + (w * 32) * XST;
#pragma unroll
        for (int ks2 = 0; ks2 < 2; ks2++) {
            const int kb = ks2 * 16 + 2 * tg;
            unsigned a0[4], a1[4];
            {
                float2 v;
                v = *(const float2*)(xs + gq * XST + kb);           a0[0] = packh2(v.x, v.y);
                v = *(const float2*)(xs + (gq + 8) * XST + kb);     a0[1] = packh2(v.x, v.y);
                v = *(const float2*)(xs + gq * XST + kb + 8);       a0[2] = packh2(v.x, v.y);
                v = *(const float2*)(xs + (gq + 8) * XST + kb + 8); a0[3] = packh2(v.x, v.y);
                v = *(const float2*)(xs + (gq + 16) * XST + kb);        a1[0] = packh2(v.x, v.y);
                v = *(const float2*)(xs + (gq + 24) * XST + kb);        a1[1] = packh2(v.x, v.y);
                v = *(const float2*)(xs + (gq + 16) * XST + kb + 8);    a1[2] = packh2(v.x, v.y);
                v = *(const float2*)(xs + (gq + 24) * XST + kb + 8);    a1[3] = packh2(v.x, v.y);
            }
            const unsigned* wb = W_sh + (c * 16 + ks2 * 8 + tg) * WST + gq;
#pragma unroll
            for (int nt = 0; nt < 8; nt++) {
                unsigned b0 = wb[nt * 8];
                unsigned b1 = wb[4 * WST + nt * 8];
                mma_f16(acc[0][nt], a0, b0, b1);
                mma_f16(acc[1][nt], a1, b0, b1);
            }
        }
        __syncthreads();
        buf ^= 1;
    }

    if (sel == 0) {
        const float scale = rsqrtf(192.0f);
        unsigned* qo = g_q + ((size_t)b * 256 + w * 32) * 32;
#pragma unroll
        for (int r = 0; r < 2; r++) {
            int r0 = r * 16 + gq;
#pragma unroll
            for (int nt = 0; nt < 8; nt++) {
                int wi = nt * 4 + tg;
                qo[r0 * 32 + wi] = packh2(acc[r][nt][0] * scale, acc[r][nt][1] * scale);
                qo[(r0 + 8) * 32 + wi] = packh2(acc[r][nt][2] * scale, acc[r][nt][3] * scale);
            }
        }
    } else if (sel == 1) {
        unsigned* ko = g_k + ((size_t)b * 256 + w * 32) * 32;
#pragma unroll
        for (int r = 0; r < 2; r++) {
            int r0 = r * 16 + gq;
#pragma unroll
            for (int nt = 0; nt < 8; nt++) {
                int wi = nt * 4 + tg;
                ko[r0 * 32 + wi] = packh2(acc[r][nt][0], acc[r][nt][1]);
                ko[(r0 + 8) * 32 + wi] = packh2(acc[r][nt][2], acc[r][nt][3]);
            }
        }
    } else {
        // v -> [h][t] half: adjacent t live in lanes gq, gq^1 (lane^4); even-gq
        // lanes pack (mine, partner) into one half2 word.
        unsigned* vo = g_vT + (size_t)b * 8192;
        const bool even = ((gq & 1) == 0);
#pragma unroll
        for (int r = 0; r < 2; r++) {
            int t0 = w * 32 + r * 16 + gq;
#pragma unroll
            for (int nt = 0; nt < 8; nt++) {
                int c = nt * 8 + 2 * tg;
                float a0 = acc[r][nt][0], a1 = acc[r][nt][1];
                float a2 = acc[r][nt][2], a3 = acc[r][nt][3];
                float p0 = __shfl_xor_sync(0xffffffffu, a0, 4);
                float p1 = __shfl_xor_sync(0xffffffffu, a1, 4);
                float p2 = __shfl_xor_sync(0xffffffffu, a2, 4);
                float p3 = __shfl_xor_sync(0xffffffffu, a3, 4);
                if (even) {
                    vo[c * 128 + (t0 >> 1)]           = packh2(a0, p0);
                    vo[(c + 1) * 128 + (t0 >> 1)]     = packh2(a1, p1);
                    vo[c * 128 + ((t0 + 8) >> 1)]     = packh2(a2, p2);
                    vo[(c + 1) * 128 + ((t0 + 8) >> 1)] = packh2(a3, p3);
                }
            }
        }
    }
}

// ---------------------------------------------------------------------------
// Kernel 2 + 3: positional projections and bias (tiny, fp32 exact)
// ---------------------------------------------------------------------------
__global__ __launch_bounds__(256) void pos_kernel(const float* __restrict__ pe,
                                                  const float* __restrict__ Wk,
                                                  const float* __restrict__ Wq) {
    int idx = blockIdx.x * 256 + threadIdx.x;
    int t = idx >> 7;
    int j = idx & 127;
    const float* __restrict__ W = (j < 64) ? Wk : Wq;
    int col = j & 63;
    float s = 0.0f;
#pragma unroll 4
    for (int c = 0; c < 192; c++) s = fmaf(pe[t * 192 + c], W[c * 64 + col], s);
    g_pos[idx] = s;
}

__global__ __launch_bounds__(256) void bias_kernel() {
    int i = blockIdx.x;
    int j = threadIdx.x;
    float s = 0.0f;
#pragma unroll 4
    for (int h = 0; h < 64; h++)
        s = fmaf(g_pos[i * 128 + h], g_pos[j * 128 + 64 + h], s);
    g_bias[i * 256 + j] = s;
}

// ---------------------------------------------------------------------------
// Kernel 4: flash-block attention, fp16 m16n8k16. Round-12 version with the
// P smem round-trip ELIMINATED: the S C-fragment layout equals the P A-frag
// layout for m16n8k16 (pa[0]=pack(e[2ks][0],e[2ks][1]), pa[1]=pack(e[2ks][2],
// e[2ks][3]), pa[2]/pa[3] from e[2ks+1]) — verified identical word-for-word
// to the old smem path. Removes 8 STS + 8 LDS + 2 syncwarps per tile.
// smem 19.5KB (K/V tiles only), 2 CTAs/SM.
// ---------------------------------------------------------------------------
#define KSW 36
#define VSW 20
__global__ __launch_bounds__(256, 2) void attn_f16_kernel(float* __restrict__ out) {
    extern __shared__ unsigned smw[];
    unsigned* kbuf[2] = { smw, smw + 1152 };          // 32*36 words each
    unsigned* vbuf[2] = { smw + 2304, smw + 3584 };   // 64*20 words each

    const int qb = blockIdx.x;
    const int b  = blockIdx.y;
    const int tid = threadIdx.x, w = tid >> 5, lane = tid & 31;
    const int gq = lane >> 2, tg = lane & 3;
    const int nj = (qb + 1) * 4;

    const unsigned* __restrict__ kg = g_k + (size_t)b * 8192;    // [t][32w]
    const unsigned* __restrict__ vg = g_vT + (size_t)b * 8192;   // [h][128w]

    const int rowg = qb * 128 + gq * 8 + w;
    const int row2 = rowg + 64;

    // Q fragments (packed half2): 16 x 32-bit loads
    unsigned qa[4][4];
    {
        const unsigned* __restrict__ qh = g_q + ((size_t)b * 256 + qb * 128) * 32;
        const int r0 = gq * 8 + w, r1 = r0 + 64;
#pragma unroll
        for (int kk = 0; kk < 4; kk++) {
            qa[kk][0] = qh[r0 * 32 + kk * 8 + tg];
            qa[kk][1] = qh[r1 * 32 + kk * 8 + tg];
            qa[kk][2] = qh[r0 * 32 + kk * 8 + tg + 4];
            qa[kk][3] = qh[r1 * 32 + kk * 8 + tg + 4];
        }
    }

    float o[8][4];
#pragma unroll
    for (int n = 0; n < 8; n++)
#pragma unroll
        for (int i = 0; i < 4; i++) o[n][i] = 0.0f;
    float m0 = -1e30f, m1 = -1e30f, l0 = 0.0f, l1 = 0.0f;

    // Prologue: stage tile 0. K: 32 rows x 8 chunks; V: 64 rows x 4 chunks.
    for (int f = tid; f < 512; f += 256) {
        if (f < 256) {
            int r = f >> 3, c8 = f & 7;
            CP_ASYNC16(smaddr(kbuf[0] + r * KSW + c8 * 4), kg + r * 32 + c8 * 4);
        } else {
            int g = f - 256;
            int h = g >> 2, c4 = g & 3;
            CP_ASYNC16(smaddr(vbuf[0] + h * VSW + c4 * 4), vg + h * 128 + c4 * 4);
        }
    }
    CP_COMMIT();

    int buf = 0;
    for (int jt = 0; jt < nj; jt++) {
        const int j0 = jt * 32;
        asm volatile("cp.async.wait_group 0;");
        __syncthreads();

        if (jt + 1 < nj) {
            const int jn = j0 + 32;
            unsigned* kn = kbuf[buf ^ 1];
            unsigned* vn = vbuf[buf ^ 1];
            for (int f = tid; f < 512; f += 256) {
                if (f < 256) {
                    int r = f >> 3, c8 = f & 7;
                    CP_ASYNC16(smaddr(kn + r * KSW + c8 * 4),
                               kg + (jn + r) * 32 + c8 * 4);
                } else {
                    int g = f - 256;
                    int h = g >> 2, c4 = g & 3;
                    CP_ASYNC16(smaddr(vn + h * VSW + c4 * 4),
                               vg + h * 128 + (jn >> 1) + c4 * 4);
                }
            }
            CP_COMMIT();
        }

        const unsigned* kb = kbuf[buf];
        const unsigned* vb = vbuf[buf];

        // Hoisted bias loads (independent of the mma chain below)
        float2 bv0[4], bv1[4];
        {
            const float* __restrict__ br0 = g_bias + (size_t)rowg * 256 + j0;
            const float* __restrict__ br1 = g_bias + (size_t)row2 * 256 + j0;
#pragma unroll
            for (int nt = 0; nt < 4; nt++) {
                int c = nt * 8 + 2 * tg;
                bv0[nt] = *(const float2*)(br0 + c);
                bv1[nt] = *(const float2*)(br1 + c);
            }
        }

        // S = Q K^T  (q pre-scaled): 16 mmas
        float s[4][4];
#pragma unroll
        for (int n = 0; n < 4; n++)
#pragma unroll
            for (int i = 0; i < 4; i++) s[n][i] = 0.0f;
#pragma unroll
        for (int kk = 0; kk < 4; kk++) {
#pragma unroll
            for (int nt = 0; nt < 4; nt++) {
                const unsigned* kb2 = kb + (nt * 8 + gq) * KSW + kk * 8 + tg;
                mma_f16(s[nt], qa[kk], kb2[0], kb2[4]);
            }
        }

        // + bias, causal mask
#pragma unroll
        for (int nt = 0; nt < 4; nt++) {
            int c = nt * 8 + 2 * tg;
            int col = j0 + c;
            s[nt][0] = (col     <= rowg) ? (s[nt][0] + bv0[nt].x) : -1e30f;
            s[nt][1] = (col + 1 <= rowg) ? (s[nt][1] + bv0[nt].y) : -1e30f;
            s[nt][2] = (col     <= row2) ? (s[nt][2] + bv1[nt].x) : -1e30f;
            s[nt][3] = (col + 1 <= row2) ? (s[nt][3] + bv1[nt].y) : -1e30f;
        }

        // online softmax
        float mx0 = -1e30f, mx1 = -1e30f;
#pragma unroll
        for (int nt = 0; nt < 4; nt++) {
            mx0 = fmaxf(mx0, fmaxf(s[nt][0], s[nt][1]));
            mx1 = fmaxf(mx1, fmaxf(s[nt][2], s[nt][3]));
        }
        mx0 = fmaxf(mx0, __shfl_xor_sync(0xffffffffu, mx0, 1));
        mx0 = fmaxf(mx0, __shfl_xor_sync(0xffffffffu, mx0, 2));
        mx1 = fmaxf(mx1, __shfl_xor_sync(0xffffffffu, mx1, 1));
        mx1 = fmaxf(mx1, __shfl_xor_sync(0xffffffffu, mx1, 2));
        float mn0 = fmaxf(m0, mx0), mn1 = fmaxf(m1, mx1);
        float al0 = __expf(m0 - mn0), al1 = __expf(m1 - mn1);
        m0 = mn0; m1 = mn1;

        float sum0 = 0.0f, sum1 = 0.0f;
        float e[4][4];
#pragma unroll
        for (int nt = 0; nt < 4; nt++) {
            e[nt][0] = __expf(s[nt][0] - mn0);
            e[nt][1] = __expf(s[nt][1] - mn0);
            e[nt][2] = __expf(s[nt][2] - mn1);
            e[nt][3] = __expf(s[nt][3] - mn1);
            sum0 += e[nt][0] + e[nt][1];
            sum1 += e[nt][2] + e[nt][3];
        }
        sum0 += __shfl_xor_sync(0xffffffffu, sum0, 1);
        sum0 += __shfl_xor_sync(0xffffffffu, sum0, 2);
        sum1 += __shfl_xor_sync(0xffffffffu, sum1, 1);
        sum1 += __shfl_xor_sync(0xffffffffu, sum1, 2);
        l0 = l0 * al0 + sum0;
        l1 = l1 * al1 + sum1;

#pragma unroll
        for (int nt = 0; nt < 8; nt++) {
            o[nt][0] *= al0; o[nt][1] *= al0;
            o[nt][2] *= al1; o[nt][3] *= al1;
        }

        // O += P V : P A-frags packed DIRECTLY from e registers (C-frag == A-frag)
#pragma unroll
        for (int ks = 0; ks < 2; ks++) {
            unsigned pa[4];
            pa[0] = packh2(e[2 * ks][0],     e[2 * ks][1]);
            pa[1] = packh2(e[2 * ks][2],     e[2 * ks][3]);
            pa[2] = packh2(e[2 * ks + 1][0], e[2 * ks + 1][1]);
            pa[3] = packh2(e[2 * ks + 1][2], e[2 * ks + 1][3]);
#pragma unroll
            for (int nt = 0; nt < 8; nt++) {
                const unsigned* vb2 = vb + (nt * 8 + gq) * VSW + ks * 8 + tg;
                mma_f16(o[nt], pa, vb2[0], vb2[4]);
            }
        }
        // no bottom __syncthreads — next iteration's top barrier orders restaging
        buf ^= 1;
    }

    float inv0 = 1.0f / l0, inv1 = 1.0f / l1;
    float* ob = out + ((size_t)b * 256) * 64;
#pragma unroll
    for (int nt = 0; nt < 8; nt++) {
        int c = nt * 8 + 2 * tg;
        *(float2*)(ob + (size_t)rowg * 64 + c) =
            make_float2(o[nt][0] * inv0, o[nt][1] * inv0);
        *(float2*)(ob + (size_t)row2 * 64 + c) =
            make_float2(o[nt][2] * inv1, o[nt][3] * inv1);
    }
}

// ---------------------------------------------------------------------------
extern "C" void kernel_launch(void* const* d_in, const int* in_sizes, int n_in,
                              void* d_out, int out_size) {
    const float* x  = (const float*)d_in[0];
    const float* Wk = (const float*)d_in[1];
    const float* Wq = (const float*)d_in[2];
    const float* Wv = (const float*)d_in[3];
    const float* pe = (const float*)d_in[4];
    float* out = (float*)d_out;
    (void)in_sizes; (void)n_in; (void)out_size;

    static bool attr_set = false;
    if (!attr_set) {
        cudaFuncSetAttribute(qkv_f16_kernel,
                             cudaFuncAttributeMaxDynamicSharedMemorySize, 109568);
        cudaFuncSetAttribute(attn_f16_kernel,
                             cudaFuncAttributeMaxDynamicSharedMemorySize, 19456);
        attr_set = true;
    }

    qkv_f16_kernel<<<dim3(3, 512), 256, 109568>>>(x, Wq, Wk, Wv);
    pos_kernel<<<128, 256>>>(pe, Wk, Wq);
    bias_kernel<<<256, 256>>>();
    attn_f16_kernel<<<dim3(2, 512), 256, 19456>>>(out);
}